// round 14
// baseline (speedup 1.0000x reference)
#include <cuda_runtime.h>
#include <cuda_fp16.h>
#include <cstdint>

// Problem constants
#define BATCH   2
#define S_LEN   1024
#define D_DIM   1024
#define NHEAD   16
#define HD      64
#define NMEM    12          // 3*L
#define SCALE   0.125f      // 1/sqrt(64)

// ---------------------------------------------------------------------------
// Scratch (device globals: allocation-free)
// ---------------------------------------------------------------------------
__device__ __align__(16) __half g_memlnh[(size_t)24576 * 1024]; // LN'd mem rows (fp16)
__device__ __align__(16) __half g_xh    [(size_t)2048 * 1024];  // fp16 x
__device__ __align__(16) __half g_wqkvh [(size_t)3072 * 1024];  // fp16 Wqkv
__device__ __align__(16) __half g_qhh   [(size_t)2048 * 1024];  // fp16 q (B,H,S,hd)
__device__ __align__(16) __half g_khh   [(size_t)2048 * 1024];  // fp16 k
__device__ __align__(16) __half g_vhh   [(size_t)2048 * 1024];  // fp16 v
__device__ __align__(16) __half g_wkT   [(size_t)1024 * 1024];  // fp16 Wk^T
__device__ __align__(16) __half g_qp    [(size_t)2048 * 16 * 1024]; // Wk^T q per (bs,h)
__device__ __align__(16) __half g_ctx   [(size_t)2048 * 16 * 1024]; // sum_m w_m*memln
__device__ __align__(16) __half g_mergedh[(size_t)2048 * 1024]; // (B*S, D) attn out fp16
__device__ __align__(16) __half g_wouth [(size_t)1024 * 1024];  // fp16 Wout
__device__ float g_ms  [(size_t)2048 * 16 * 12];  // mem scores
__device__ float g_pmn [(size_t)2048 * 16 * 12];  // normalized mem weights
__device__ float g_qb  [(size_t)2048 * 16];       // q . bk_h
__device__ float g_psum[(size_t)2048 * 16];       // sum_m pmn

// ---------------------------------------------------------------------------
// Helpers
// ---------------------------------------------------------------------------
__device__ __forceinline__ uint32_t smem_u32(const void* p) {
    uint32_t a;
    asm("{ .reg .u64 t; cvta.to.shared.u64 t, %1; cvt.u32.u64 %0, t; }" : "=r"(a) : "l"(p));
    return a;
}
__device__ __forceinline__ void cp16(uint32_t dst, const void* src) {
    asm volatile("cp.async.cg.shared.global [%0], [%1], 16;" :: "r"(dst), "l"(src));
}
__device__ __forceinline__ void ldsm4(uint32_t* r, uint32_t addr) {
    asm volatile("ldmatrix.sync.aligned.m8n8.x4.shared.b16 {%0,%1,%2,%3}, [%4];"
                 : "=r"(r[0]), "=r"(r[1]), "=r"(r[2]), "=r"(r[3]) : "r"(addr));
}
__device__ __forceinline__ void ldsm4t(uint32_t* r, uint32_t addr) {
    asm volatile("ldmatrix.sync.aligned.m8n8.x4.trans.shared.b16 {%0,%1,%2,%3}, [%4];"
                 : "=r"(r[0]), "=r"(r[1]), "=r"(r[2]), "=r"(r[3]) : "r"(addr));
}
__device__ __forceinline__ void mma16(float* c, const uint32_t* a, const uint32_t* b) {
    asm volatile("mma.sync.aligned.m16n8k16.row.col.f32.f16.f16.f32 "
                 "{%0,%1,%2,%3}, {%4,%5,%6,%7}, {%8,%9}, {%0,%1,%2,%3};"
                 : "+f"(c[0]), "+f"(c[1]), "+f"(c[2]), "+f"(c[3])
                 : "r"(a[0]), "r"(a[1]), "r"(a[2]), "r"(a[3]), "r"(b[0]), "r"(b[1]));
}
__device__ __forceinline__ uint32_t packh2(float a, float b) {
    __half2 h = __floats2half2_rn(a, b);
    return *(uint32_t*)&h;
}

// ===========================================================================
// fp16 GEMM (NT) — GEMM1 only: qkv projection with scatter epilogue
// ===========================================================================
#define GF_ASTG 36864u
#define GF_BSTG 18432u
#define GF_SMEM 165888

__global__ void __launch_bounds__(256, 1)
gemm_qkv(const __half* __restrict__ A, const __half* __restrict__ B,
         const float* __restrict__ bias,
         float* __restrict__ oQ, float* __restrict__ oK, float* __restrict__ oV,
         __half* __restrict__ oQh, __half* __restrict__ oKh, __half* __restrict__ oVh)
{
    extern __shared__ char smemc[];
    const uint32_t aBase = smem_u32(smemc);
    const uint32_t bBase = aBase + 3u * GF_ASTG;
    const int K = 1024;

    const int tid = threadIdx.x;
    const int lane = tid & 31, wid = tid >> 5;
    const int m0 = blockIdx.y << 8;
    const int n0 = blockIdx.x << 7;
    const int wm = (wid & 3) << 6;
    const int wn = (wid >> 2) << 6;

    const int grow = tid >> 3;
    const int gc8  = (tid & 7) << 3;
    const __half* Ag = A + (size_t)(m0 + grow) * K + gc8;
    const __half* Bg = B + (size_t)(n0 + grow) * K + gc8;
    const uint32_t sOff = (uint32_t)((grow * 72 + gc8) << 1);

    const int rA = lane & 15, cA = (lane >> 4) << 3;
    const int rB = (lane & 7) + ((lane >> 4) << 3);
    const int cB = ((lane >> 3) & 1) << 3;

#define GF_LOAD(stage, kb) do {                                                \
    const __half* _a = Ag + ((kb) << 6);                                       \
    const __half* _b = Bg + ((kb) << 6);                                       \
    const uint32_t _da = aBase + (uint32_t)(stage) * GF_ASTG + sOff;           \
    const uint32_t _db = bBase + (uint32_t)(stage) * GF_BSTG + sOff;           \
    _Pragma("unroll")                                                          \
    for (int _p = 0; _p < 8; _p++)                                             \
        cp16(_da + (uint32_t)_p * 4608u, _a + (size_t)(_p << 5) * K);          \
    _Pragma("unroll")                                                          \
    for (int _p = 0; _p < 4; _p++)                                             \
        cp16(_db + (uint32_t)_p * 4608u, _b + (size_t)(_p << 5) * K);          \
    asm volatile("cp.async.commit_group;" ::: "memory");                       \
} while (0)

    float c[4][8][4];
#pragma unroll
    for (int i = 0; i < 4; i++)
#pragma unroll
        for (int j = 0; j < 8; j++)
#pragma unroll
            for (int r = 0; r < 4; r++) c[i][j][r] = 0.f;

    const int NK = 16;
    GF_LOAD(0, 0);
    GF_LOAD(1, 1);

    for (int kb = 0; kb < NK; ++kb) {
        if (kb < NK - 1)
            asm volatile("cp.async.wait_group 1;" ::: "memory");
        else
            asm volatile("cp.async.wait_group 0;" ::: "memory");
        __syncthreads();

        if (kb + 2 < NK) {
            int ns = kb + 2; ns = ns - (ns / 3) * 3;
            GF_LOAD(ns, kb + 2);
        }

        int st = kb - (kb / 3) * 3;
        const uint32_t aS = aBase + (uint32_t)st * GF_ASTG;
        const uint32_t bS = bBase + (uint32_t)st * GF_BSTG;

#pragma unroll
        for (int ks = 0; ks < 4; ++ks) {
            uint32_t a[4][4];
#pragma unroll
            for (int i = 0; i < 4; i++)
                ldsm4(a[i], aS + (uint32_t)(((wm + i * 16 + rA) * 72 + cA + ks * 16) << 1));
            uint32_t b[8][2];
#pragma unroll
            for (int j2 = 0; j2 < 4; j2++) {
                uint32_t r4[4];
                ldsm4(r4, bS + (uint32_t)(((wn + j2 * 16 + rB) * 72 + cB + ks * 16) << 1));
                b[2 * j2 + 0][0] = r4[0]; b[2 * j2 + 0][1] = r4[1];
                b[2 * j2 + 1][0] = r4[2]; b[2 * j2 + 1][1] = r4[3];
            }
#pragma unroll
            for (int i = 0; i < 4; i++)
#pragma unroll
                for (int j = 0; j < 8; j++)
                    mma16(c[i][j], a[i], b[j]);
        }
    }
#undef GF_LOAD

    const int gro = lane >> 2;
    const int gco = (lane & 3) << 1;
#pragma unroll
    for (int i = 0; i < 4; i++) {
        const int r0 = m0 + wm + i * 16 + gro;
#pragma unroll
        for (int j = 0; j < 8; j++) {
            const int col = n0 + wn + j * 8 + gco;
            const float b0 = bias[col], b1 = bias[col + 1];
            const int part = col >> 10;
            const int rem  = col & 1023;
            const int h = rem >> 6, d = rem & 63;
            float* dst = (part == 0) ? oQ : (part == 1) ? oK : oV;
            __half* dsth = (part == 0) ? oQh : (part == 1) ? oKh : oVh;
#pragma unroll
            for (int half = 0; half < 2; half++) {
                const int row = r0 + half * 8;
                const int bb = row >> 10, s = row & 1023;
                float vx = c[i][j][2 * half] + b0;
                float vy = c[i][j][2 * half + 1] + b1;
                const size_t idx = (size_t)(((bb * NHEAD + h) << 10) + s) * HD + d;
                *(float2*)(dst + idx) = make_float2(vx, vy);
                *(__half2*)(dsth + idx) = __floats2half2_rn(vx, vy);
            }
        }
    }
}

// ===========================================================================
// gemm_h16 — fp16 128x128 GEMM (NT) for GEMM3: out = merged @ Wout^T + bout
// BK=64 halves, 2-stage cp.async, 256 thr (8 warps 2x4), fp32 C store.
// ===========================================================================
#define GH_STG  18432u
#define GH_SMEM 73728

__global__ void __launch_bounds__(256)
gemm_h16(const __half* __restrict__ A, const __half* __restrict__ B,
         const float* __restrict__ bias, float* __restrict__ C,
         int M, int N, int K)
{
    extern __shared__ char smemc[];
    const uint32_t aBase = smem_u32(smemc);
    const uint32_t bBase = aBase + 2u * GH_STG;

    const int tid = threadIdx.x;
    const int lane = tid & 31, wid = tid >> 5;
    const int m0 = blockIdx.y << 7, n0 = blockIdx.x << 7;
    const int wm = (wid & 1) << 6;     // 2 warps on m
    const int wn = (wid >> 1) << 5;    // 4 warps on n (32 cols each)

    const int grow = tid >> 1;
    const int gc = (tid & 1) << 5;     // 0 / 32 halves
    const __half* Ag = A + (size_t)(m0 + grow) * K + gc;
    const __half* Bg = B + (size_t)(n0 + grow) * K + gc;
    const uint32_t sOff = (uint32_t)((grow * 72 + gc) << 1);

    const int rA = lane & 15, cA = (lane >> 4) << 3;
    const int rB = (lane & 7) + ((lane >> 4) << 3);
    const int cB = ((lane >> 3) & 1) << 3;

#define GH_LOAD(st, kb) do {                                                   \
    const __half* _a = Ag + ((kb) << 6);                                       \
    const __half* _b = Bg + ((kb) << 6);                                       \
    uint32_t _da = aBase + (uint32_t)(st) * GH_STG + sOff;                     \
    uint32_t _db = bBase + (uint32_t)(st) * GH_STG + sOff;                     \
    cp16(_da, _a); cp16(_da + 16, _a + 8);                                     \
    cp16(_da + 32, _a + 16); cp16(_da + 48, _a + 24);                          \
    cp16(_db, _b); cp16(_db + 16, _b + 8);                                     \
    cp16(_db + 32, _b + 16); cp16(_db + 48, _b + 24);                          \
    asm volatile("cp.async.commit_group;" ::: "memory");                       \
} while (0)

    float c[4][4][4];
#pragma unroll
    for (int i = 0; i < 4; i++)
#pragma unroll
        for (int j = 0; j < 4; j++)
#pragma unroll
            for (int r = 0; r < 4; r++) c[i][j][r] = 0.f;

    const int NK = K >> 6;
    GH_LOAD(0, 0);
    GH_LOAD(1, 1);

    for (int it = 0; it < NK; ++it) {
        if (it + 2 < NK)
            asm volatile("cp.async.wait_group 1;" ::: "memory");
        else
            asm volatile("cp.async.wait_group 0;" ::: "memory");
        __syncthreads();

        const int st = it & 1;
        const uint32_t aS = aBase + (uint32_t)st * GH_STG;
        const uint32_t bS = bBase + (uint32_t)st * GH_STG;

#pragma unroll
        for (int ks = 0; ks < 4; ++ks) {
            uint32_t a[4][4];
#pragma unroll
            for (int i = 0; i < 4; i++)
                ldsm4(a[i], aS + (uint32_t)(((wm + i * 16 + rA) * 72 + cA + ks * 16) << 1));
            uint32_t b[4][2];
#pragma unroll
            for (int j2 = 0; j2 < 2; j2++) {
                uint32_t r4[4];
                ldsm4(r4, bS + (uint32_t)(((wn + j2 * 16 + rB) * 72 + cB + ks * 16) << 1));
                b[2 * j2 + 0][0] = r4[0]; b[2 * j2 + 0][1] = r4[1];
                b[2 * j2 + 1][0] = r4[2]; b[2 * j2 + 1][1] = r4[3];
            }
#pragma unroll
            for (int i = 0; i < 4; i++)
#pragma unroll
                for (int j = 0; j < 4; j++)
                    mma16(c[i][j], a[i], b[j]);
        }
        __syncthreads();
        if (it + 2 < NK) GH_LOAD(st, it + 2);
    }
#undef GH_LOAD

    const int gro = lane >> 2;
    const int gco = (lane & 3) << 1;
#pragma unroll
    for (int i = 0; i < 4; i++) {
        const int r0 = m0 + wm + i * 16 + gro;
#pragma unroll
        for (int j = 0; j < 4; j++) {
            const int col = n0 + wn + j * 8 + gco;
            const float b0 = bias[col], b1 = bias[col + 1];
            float2 v0 = make_float2(c[i][j][0] + b0, c[i][j][1] + b1);
            float2 v1 = make_float2(c[i][j][2] + b0, c[i][j][3] + b1);
            *(float2*)(C + (size_t)r0 * N + col) = v0;
            *(float2*)(C + (size_t)(r0 + 8) * N + col) = v1;
        }
    }
}

// ---------------------------------------------------------------------------
// conversion / transpose kernels
// ---------------------------------------------------------------------------
__global__ void cvt_fp16_kernel(const float4* __restrict__ in, __half2* __restrict__ out)
{
    int i = blockIdx.x * blockDim.x + threadIdx.x;
    float4 v = in[i];
    out[2 * i + 0] = __floats2half2_rn(v.x, v.y);
    out[2 * i + 1] = __floats2half2_rn(v.z, v.w);
}
// Wk^T: o[n][j] = Wk[j][n]  (Wk = Wqkv rows 1024..2047), fp16 output
__global__ void k_wkT(const float* __restrict__ wk, __half* __restrict__ o)
{
    __shared__ float t[32][33];
    int x = (blockIdx.x << 5) + threadIdx.x;   // input col n
    int y = (blockIdx.y << 5) + threadIdx.y;   // input row j
#pragma unroll
    for (int i = 0; i < 32; i += 8)
        t[threadIdx.y + i][threadIdx.x] = wk[(size_t)(y + i) * 1024 + x];
    __syncthreads();
    x = (blockIdx.y << 5) + threadIdx.x;       // out col j
    y = (blockIdx.x << 5) + threadIdx.y;       // out row n
#pragma unroll
    for (int i = 0; i < 32; i += 8)
        o[(size_t)(y + i) * 1024 + x] = __float2half_rn(t[threadIdx.x][threadIdx.y + i]);
}

// ---------------------------------------------------------------------------
// Gather mem rows + LayerNorm -> fp16  (float4 per thread)
// ---------------------------------------------------------------------------
__device__ __forceinline__ float blockReduceSum(float v, float* red)
{
    __syncthreads();
    int lane = threadIdx.x & 31, wid = threadIdx.x >> 5;
#pragma unroll
    for (int o = 16; o; o >>= 1) v += __shfl_xor_sync(0xffffffffu, v, o);
    if (lane == 0) red[wid] = v;
    __syncthreads();
    if (wid == 0) {
        v = (lane < 8) ? red[lane] : 0.f;
#pragma unroll
        for (int o = 4; o; o >>= 1) v += __shfl_xor_sync(0xffffffffu, v, o);
        if (lane == 0) red[0] = v;
    }
    __syncthreads();
    return red[0];
}

__global__ void mem_ln_kernel(const float* __restrict__ pq,
                              const float* __restrict__ pk,
                              const float* __restrict__ pv)
{
    __shared__ float red[32];
    int row = blockIdx.x;
    int j  = row % NMEM;
    int bs = row / NMEM;
    int s = bs & 1023, b = bs >> 10;
    int l = j & 3;
    const float* src = (j < 4) ? pq : (j < 8) ? pk : pv;
    size_t base = (size_t)(l * BATCH + b) * (NHEAD * S_LEN * HD) + (size_t)s * HD;

    const int t = threadIdx.x;
    const int c0 = t << 2;              // 4 consecutive cols, same head chunk
    const int h = c0 >> 6, d = c0 & 63;
    float4 v = __ldg((const float4*)(src + base + (size_t)h * (S_LEN * HD) + d));
    float sum = v.x + v.y + v.z + v.w;
    sum = blockReduceSum(sum, red);
    float mean = sum * (1.f / 1024.f);
    float4 dv = make_float4(v.x - mean, v.y - mean, v.z - mean, v.w - mean);
    float sq = dv.x * dv.x + dv.y * dv.y + dv.z * dv.z + dv.w * dv.w;
    sq = blockReduceSum(sq, red);
    float inv = rsqrtf(sq * (1.f / 1024.f) + 1e-5f);

    __half* orow = g_memlnh + (size_t)row * 1024;
    __half2 h0 = __floats2half2_rn(dv.x * inv, dv.y * inv);
    __half2 h1 = __floats2half2_rn(dv.z * inv, dv.w * inv);
    *(__half2*)(orow + c0)     = h0;
    *(__half2*)(orow + c0 + 2) = h1;
}

// ===========================================================================
// k_qp: qp[(bs,h),n] = sum_d q[b,h,s,d] * WkT[n, h*64+d]   (per-head proj)
// ===========================================================================
__global__ void __launch_bounds__(256)
k_qp(const __half* __restrict__ q, const __half* __restrict__ wkT,
     __half* __restrict__ qp)
{
    __shared__ __half sA[128 * 72];
    __shared__ __half sB[128 * 72];
    const int tid = threadIdx.x, lane = tid & 31, wid = tid >> 5;
    const int z = blockIdx.z, b = z >> 4, h = z & 15;
    const int m0 = blockIdx.y << 7, n0 = blockIdx.x << 7;
    const uint32_t aB = smem_u32(sA), bB = smem_u32(sB);

    {
        const int grow = tid >> 1, gc = (tid & 1) << 5;
        const __half* aSrc = q + ((size_t)z << 16) + ((size_t)(m0 + grow) << 6) + gc;
        const __half* bSrc = wkT + (size_t)(n0 + grow) * 1024 + (h << 6) + gc;
        uint32_t da = aB + (uint32_t)((grow * 72 + gc) << 1);
        uint32_t db = bB + (uint32_t)((grow * 72 + gc) << 1);
        cp16(da, aSrc); cp16(da + 16, aSrc + 8);
        cp16(da + 32, aSrc + 16); cp16(da + 48, aSrc + 24);
        cp16(db, bSrc); cp16(db + 16, bSrc + 8);
        cp16(db + 32, bSrc + 16); cp16(db + 48, bSrc + 24);
        asm volatile("cp.async.commit_group;\ncp.async.wait_group 0;" ::: "memory");
    }
    __syncthreads();

    const int wm = (wid & 1) << 6, wn = (wid >> 1) << 5;
    const int rA = lane & 15, cA = (lane >> 4) << 3;
    const int rB = (lane & 7) + ((lane >> 4) << 3);
    const int cB = ((lane >> 3) & 1) << 3;

    float c[4][4][4];
#pragma unroll
    for (int i = 0; i < 4; i++)
#pragma unroll
        for (int j = 0; j < 4; j++)
#pragma unroll
            for (int r = 0; r < 4; r++) c[i][j][r] = 0.f;

#pragma unroll
    for (int ks = 0; ks < 4; ++ks) {
        uint32_t a[4][4];
#pragma unroll
        for (int i = 0; i < 4; i++)
            ldsm4(a[i], aB + (uint32_t)(((wm + i * 16 + rA) * 72 + cA + ks * 16) << 1));
        uint32_t bb[4][2];
#pragma unroll
        for (int j2 = 0; j2 < 2; j2++) {
            uint32_t r4[4];
            ldsm4(r4, bB + (uint32_t)(((wn + j2 * 16 + rB) * 72 + cB + ks * 16) << 1));
            bb[2 * j2 + 0][0] = r4[0]; bb[2 * j2 + 0][1] = r4[1];
            bb[2 * j2 + 1][0] = r4[2]; bb[2 * j2 + 1][1] = r4[3];
        }
#pragma unroll
        for (int i = 0; i < 4; i++)
#pragma unroll
            for (int j = 0; j < 4; j++)
                mma16(c[i][j], a[i], bb[j]);
    }

    const int gro = lane >> 2, gco = (lane & 3) << 1;
#pragma unroll
    for (int i = 0; i < 4; i++) {
        const int row = m0 + wm + i * 16 + gro;
        __half* d0 = qp + ((size_t)((b << 10) + row) * 16 + h) * 1024;
        __half* d1 = d0 + (size_t)8 * 16 * 1024;   // row+8
#pragma unroll
        for (int j = 0; j < 4; j++) {
            const int col = n0 + wn + j * 8 + gco;
            *(__half2*)(d0 + col) = __floats2half2_rn(c[i][j][0], c[i][j][1]);
            *(__half2*)(d1 + col) = __floats2half2_rn(c[i][j][2], c[i][j][3]);
        }
    }
}

// ===========================================================================
// k_qb: qb[(bs,h)] = q[b,h,s,:] . bqkv[1024 + h*64 ..]
// ===========================================================================
__global__ void k_qb(const __half* __restrict__ q, const float* __restrict__ bqkv,
                     float* __restrict__ qb)
{
    __shared__ float sbk[64];
    const int z = blockIdx.x, b = z >> 4, h = z & 15;
    if (threadIdx.x < 64) sbk[threadIdx.x] = bqkv[1024 + (h << 6) + threadIdx.x];
    __syncthreads();
    for (int s = threadIdx.x; s < 1024; s += 256) {
        const __half2* qr = (const __half2*)(q + ((size_t)z << 16) + ((size_t)s << 6));
        float acc = 0.f;
#pragma unroll
        for (int i = 0; i < 32; i++) {
            float2 f = __half22float2(qr[i]);
            acc += f.x * sbk[2 * i] + f.y * sbk[2 * i + 1];
        }
        qb[(size_t)((b << 10) + s) * 16 + h] = acc;
    }
}

// ===========================================================================
// k_ms: mem scores[(bs,h),m] = (qp[bs,h,:].memln[bs,m,:] + qb)*SCALE
// ===========================================================================
__global__ void __launch_bounds__(512)
k_ms(const __half* __restrict__ qp, const __half* __restrict__ memln,
     const float* __restrict__ qb, float* __restrict__ ms)
{
    __shared__ __align__(16) __half sm[12 * 1024];
    const int bs = blockIdx.x;
    const int tid = threadIdx.x, lane = tid & 31, w = tid >> 5;
    const __half* mlb = memln + (size_t)bs * 12288;
    for (int u = tid; u < 1536; u += 512)
        ((float4*)sm)[u] = ((const float4*)mlb)[u];

    const __half* qpr = qp + ((size_t)bs * 16 + w) * 1024;
    float4 qf[4];
#pragma unroll
    for (int i = 0; i < 4; i++) qf[i] = ((const float4*)qpr)[i * 32 + lane];
    __syncthreads();

    const float qbv = qb[(size_t)bs * 16 + w];
#pragma unroll
    for (int m = 0; m < NMEM; m++) {
        float acc = 0.f;
#pragma unroll
        for (int i = 0; i < 4; i++) {
            float4 mf = ((const float4*)sm)[m * 128 + i * 32 + lane];
            const __half2* qh2 = (const __half2*)&qf[i];
            const __half2* mh2 = (const __half2*)&mf;
#pragma unroll
            for (int jj = 0; jj < 4; jj++) {
                float2 a = __half22float2(qh2[jj]);
                float2 c2 = __half22float2(mh2[jj]);
                acc += a.x * c2.x + a.y * c2.y;
            }
        }
#pragma unroll
        for (int o = 16; o; o >>= 1) acc += __shfl_xor_sync(0xffffffffu, acc, o);
        if (lane == 0) ms[((size_t)bs * 16 + w) * 12 + m] = (acc + qbv) * SCALE;
    }
}

// ===========================================================================
// Flash attention (fp16 tc) token part + merge with precomputed mem scores.
// merged output now fp16.
// ===========================================================================
__global__ void __launch_bounds__(128)
attn_fa(const __half* __restrict__ qh, const __half* __restrict__ kh,
        const __half* __restrict__ vh, const float* __restrict__ ms,
        float* __restrict__ pmn, __half* __restrict__ merged)
{
    __shared__ __half sQ[64 * 72];
    __shared__ __half sK[2][64 * 72];
    __shared__ __half sV[2][64 * 72];

    const int tid = threadIdx.x;
    const int lane = tid & 31, w = tid >> 5;
    const int bh = blockIdx.x, b = bh >> 4, h = bh & 15;
    const int qt = gridDim.y - 1 - blockIdx.y;
    const int q0 = qt << 6;
    const int wr = w << 4;

    const uint32_t sQb = smem_u32(sQ);
    const uint32_t sKb = smem_u32(sK);
    const uint32_t sVb = smem_u32(sV);

    const int lrow = tid >> 1;
    const int lcol = (tid & 1) << 5;
    const __half* qg = qh + ((size_t)bh << 16);
    const __half* kg = kh + ((size_t)bh << 16);
    const __half* vg = vh + ((size_t)bh << 16);

#define LOADKV(bf, kt_) do {                                                   \
    const __half* _ks = kg + (((kt_) * 64 + lrow) << 6) + lcol;                \
    const __half* _vs = vg + (((kt_) * 64 + lrow) << 6) + lcol;                \
    uint32_t _kd = sKb + (uint32_t)(bf) * 9216u + ((lrow * 72 + lcol) << 1);   \
    uint32_t _vd = sVb + (uint32_t)(bf) * 9216u + ((lrow * 72 + lcol) << 1);   \
    cp16(_kd, _ks); cp16(_kd + 16, _ks + 8);                                   \
    cp16(_kd + 32, _ks + 16); cp16(_kd + 48, _ks + 24);                        \
    cp16(_vd, _vs); cp16(_vd + 16, _vs + 8);                                   \
    cp16(_vd + 32, _vs + 16); cp16(_vd + 48, _vs + 24);                        \
    asm volatile("cp.async.commit_group;" ::: "memory");                       \
} while (0)

    {
        const __half* src = qg + ((q0 + lrow) << 6) + lcol;
        uint32_t dst = sQb + ((lrow * 72 + lcol) << 1);
        cp16(dst, src); cp16(dst + 16, src + 8);
        cp16(dst + 32, src + 16); cp16(dst + 48, src + 24);
    }
    LOADKV(0, 0);
    asm volatile("cp.async.wait_group 0;" ::: "memory");
    __syncthreads();

    uint32_t qa[4][4];
    {
        const int qm = lane >> 3, qr = lane & 7;
        const int qrow = wr + ((qm & 1) << 3) + qr;
        const int qcb = (qm >> 1) << 3;
#pragma unroll
        for (int ki = 0; ki < 4; ki++)
            ldsm4(qa[ki], sQb + ((qrow * 72 + qcb + ki * 16) << 1));
    }

    const int km = lane >> 3, kr = lane & 7;
    const int kro = ((km >> 1) & 1) << 3;
    const int kco = (km & 1) << 3;
    const int vko = (km & 1) << 3;
    const int vco = ((km >> 1) & 1) << 3;

    float o[8][4];
#pragma unroll
    for (int j = 0; j < 8; j++)
#pragma unroll
        for (int e = 0; e < 4; e++) o[j][e] = 0.f;
    float mrow[2] = { -1e30f, -1e30f };
    float lrow_[2] = { 0.f, 0.f };

    const int rlane = lane >> 2, clane = (lane & 3) << 1;

    for (int kt = 0; kt <= qt; ++kt) {
        if (kt < qt) {
            LOADKV((kt + 1) & 1, kt + 1);
            asm volatile("cp.async.wait_group 1;" ::: "memory");
        } else {
            asm volatile("cp.async.wait_group 0;" ::: "memory");
        }
        __syncthreads();

        const uint32_t kS = sKb + (uint32_t)(kt & 1) * 9216u;
        const uint32_t vS = sVb + (uint32_t)(kt & 1) * 9216u;

        float sc[8][4];
#pragma unroll
        for (int j = 0; j < 8; j++)
#pragma unroll
            for (int e = 0; e < 4; e++) sc[j][e] = 0.f;

#pragma unroll
        for (int ks = 0; ks < 4; ++ks) {
#pragma unroll
            for (int j2 = 0; j2 < 4; ++j2) {
                uint32_t kb[4];
                ldsm4(kb, kS + (((j2 * 16 + kro + kr) * 72 + ks * 16 + kco) << 1));
                mma16(sc[2 * j2], qa[ks], kb);
                mma16(sc[2 * j2 + 1], qa[ks], kb + 2);
            }
        }

#pragma unroll
        for (int j = 0; j < 8; j++)
#pragma unroll
            for (int e = 0; e < 4; e++) sc[j][e] *= SCALE;
        if (kt == qt) {
            const int r0 = wr + rlane;
#pragma unroll
            for (int j = 0; j < 8; j++) {
                const int c0 = 8 * j + clane;
                if (c0 > r0)     sc[j][0] = -1e30f;
                if (c0 + 1 > r0) sc[j][1] = -1e30f;
                if (c0 > r0 + 8)     sc[j][2] = -1e30f;
                if (c0 + 1 > r0 + 8) sc[j][3] = -1e30f;
            }
        }

        float t0 = -1e30f, t1 = -1e30f;
#pragma unroll
        for (int j = 0; j < 8; j++) {
            t0 = fmaxf(t0, fmaxf(sc[j][0], sc[j][1]));
            t1 = fmaxf(t1, fmaxf(sc[j][2], sc[j][3]));
        }
        t0 = fmaxf(t0, __shfl_xor_sync(0xffffffffu, t0, 1));
        t0 = fmaxf(t0, __shfl_xor_sync(0xffffffffu, t0, 2));
        t1 = fmaxf(t1, __shfl_xor_sync(0xffffffffu, t1, 1));
        t1 = fmaxf(t1, __shfl_xor_sync(0xffffffffu, t1, 2));
        const float mn0 = fmaxf(mrow[0], t0), mn1 = fmaxf(mrow[1], t1);
        const float cr0 = __expf(mrow[0] - mn0), cr1 = __expf(mrow[1] - mn1);
        float s0 = 0.f, s1 = 0.f;
#pragma unroll
        for (int j = 0; j < 8; j++) {
            sc[j][0] = __expf(sc[j][0] - mn0);
            sc[j][1] = __expf(sc[j][1] - mn0);
            sc[j][2] = __expf(sc[j][2] - mn1);
            sc[j][3] = __expf(sc[j][3] - mn1);
            s0 += sc[j][0] + sc[j][1];
            s1 += sc[j][2] + sc[j][3];
        }
        s0 += __shfl_xor_sync(0xffffffffu, s0, 1);
        s0 += __shfl_xor_sync(0xffffffffu, s0, 2);
        s1 += __shfl_xor_sync(0xffffffffu, s1, 1);
        s1 += __shfl_xor_sync(0xffffffffu, s1, 2);
        lrow_[0] = lrow_[0] * cr0 + s0;
        lrow_[1] = lrow_[1] * cr1 + s1;
        mrow[0] = mn0; mrow[1] = mn1;
#pragma unroll
        for (int j = 0; j < 8; j++) {
            o[j][0] *= cr0; o[j][1] *= cr0;
            o[j][2] *= cr1; o[j][3] *= cr1;
        }

#pragma unroll
        for (int kc = 0; kc < 4; ++kc) {
            uint32_t pa[4];
            pa[0] = packh2(sc[2 * kc][0], sc[2 * kc][1]);
            pa[1] = packh2(sc[2 * kc][2], sc[2 * kc][3]);
            pa[2] = packh2(sc[2 * kc + 1][0], sc[2 * kc + 1][1]);
            pa[3] = packh2(sc[2 * kc + 1][2], sc[2 * kc + 1][3]);
#pragma unroll
            for (int j2 = 0; j2 < 4; ++j2) {
                uint32_t vb[4];
                ldsm4t(vb, vS + (((kc * 16 + vko + kr) * 72 + j2 * 16 + vco) << 1));
                mma16(o[2 * j2], pa, vb);
                mma16(o[2 * j2 + 1], pa, vb + 2);
            }
        }
        __syncthreads();
    }
#undef LOADKV

    // merge precomputed memory scores; write token part (fp16) + weights
#pragma unroll
    for (int hh = 0; hh < 2; hh++) {
        const int s_idx = q0 + wr + rlane + (hh << 3);
        const size_t bsh = (size_t)((b << 10) + s_idx) * 16 + h;
        const float* msp = ms + bsh * 12;
        float smv[12];
#pragma unroll
        for (int m = 0; m < NMEM; m++) smv[m] = msp[m];
        float mx = smv[0];
#pragma unroll
        for (int m = 1; m < NMEM; m++) mx = fmaxf(mx, smv[m]);
        const float mn = fmaxf(mrow[hh], mx);
        const float corr = __expf(mrow[hh] - mn);
        float p[12], ps = 0.f;
#pragma unroll
        for (int m = 0; m < NMEM; m++) { p[m] = __expf(smv[m] - mn); ps += p[m]; }
        const float lf = lrow_[hh] * corr + ps;
        const float inv = 1.f / lf;
        const float cf = corr * inv;
        if ((lane & 3) == 0) {
            float* pw = pmn + bsh * 12;
#pragma unroll
            for (int m = 0; m < NMEM; m++) pw[m] = p[m] * inv;
        }
        __half* op = merged + ((size_t)((b << 10) + s_idx) << 10) + (h << 6);
#pragma unroll
        for (int j = 0; j < 8; j++)
            *(__half2*)(op + 8 * j + clane) =
                __floats2half2_rn(o[j][2 * hh] * cf, o[j][2 * hh + 1] * cf);
    }
}

// ===========================================================================
// k_ctx: ctx[(bs,h),k] = sum_m pmn[(bs,h),m]*memln[bs,m,k]; psum[(bs,h)]
// ===========================================================================
__global__ void __launch_bounds__(256)
k_ctx(const float* __restrict__ pmn, const __half* __restrict__ memln,
      __half* __restrict__ ctx, float* __restrict__ psum)
{
    __shared__ __align__(16) __half sm[12 * 1024];
    __shared__ float sp[192];
    const int bs = blockIdx.x, tid = threadIdx.x;
    const __half* mlb = memln + (size_t)bs * 12288;
    for (int u = tid; u < 1536; u += 256)
        ((float4*)sm)[u] = ((const float4*)mlb)[u];
    if (tid < 192) sp[tid] = pmn[(size_t)bs * 192 + tid];
    __syncthreads();
    if (tid < 16) {
        float s = 0.f;
#pragma unroll
        for (int m = 0; m < NMEM; m++) s += sp[tid * 12 + m];
        psum[(size_t)bs * 16 + tid] = s;
    }
    float mv[12][4];
#pragma unroll
    for (int m = 0; m < NMEM; m++) {
        float2 fx = __half22float2(*(__half2*)&sm[m * 1024 + (tid << 2)]);
        float2 fy = __half22float2(*(__half2*)&sm[m * 1024 + (tid << 2) + 2]);
        mv[m][0] = fx.x; mv[m][1] = fx.y; mv[m][2] = fy.x; mv[m][3] = fy.y;
    }
#pragma unroll
    for (int h = 0; h < 16; h++) {
        float o0 = 0.f, o1 = 0.f, o2 = 0.f, o3 = 0.f;
#pragma unroll
        for (int m = 0; m < NMEM; m++) {
            const float p = sp[h * 12 + m];
            o0 += p * mv[m][0]; o1 += p * mv[m][1];
            o2 += p * mv[m][2]; o3 += p * mv[m][3];
        }
        __half2* dst = (__half2*)(ctx + ((size_t)bs * 16 + h) * 1024 + (tid << 2));
        dst[0] = __floats2half2_rn(o0, o1);
        dst[1] = __floats2half2_rn(o2, o3);
    }
}

// ===========================================================================
// k_wv: merged[bs, h*64+d] += sum_k Wv[h*64+d,k]*ctx[(bs,h),k] + psum*bv
// merged is fp16 read-modify-write now.
// ===========================================================================
#define WV_ASTG 18432u
#define WV_BSTG 9216u
#define WV_SMEM (2 * (WV_ASTG + WV_BSTG))

__global__ void __launch_bounds__(256)
k_wv(const __half* __restrict__ ctx, const __half* __restrict__ wqkvh,
     const float* __restrict__ psum, const float* __restrict__ bqkv,
     __half* __restrict__ merged)
{
    extern __shared__ char smemc[];
    const uint32_t aB = smem_u32(smemc);
    const uint32_t bB = aB + 2u * WV_ASTG;
    __shared__ float sbv[64];

    const int tid = threadIdx.x, lane = tid & 31, wid = tid >> 5;
    const int m0 = blockIdx.x << 7, h = blockIdx.y;
    if (tid < 64) sbv[tid] = bqkv[2048 + (h << 6) + tid];

    const __half* A = ctx + (size_t)h * 1024;             // row stride 16384
    const __half* B = wqkvh + (size_t)(2048 + (h << 6)) * 1024;

    const int agrow = tid >> 1, agc = (tid & 1) << 5;
    const int bgrow = tid >> 2, bgc = (tid & 3) << 4;

#define WV_LOAD(st, kb) do {                                                   \
    const __half* _a = A + (size_t)(m0 + agrow) * 16384 + ((kb) << 6) + agc;   \
    const __half* _b = B + (size_t)bgrow * 1024 + ((kb) << 6) + bgc;           \
    uint32_t _da = aB + (uint32_t)(st) * WV_ASTG + ((agrow * 72 + agc) << 1);  \
    uint32_t _db = bB + (uint32_t)(st) * WV_BSTG + ((bgrow * 72 + bgc) << 1);  \
    cp16(_da, _a); cp16(_da + 16, _a + 8);                                     \
    cp16(_da + 32, _a + 16); cp16(_da + 48, _a + 24);                          \
    cp16(_db, _b); cp16(_db + 16, _b + 8);                                     \
    asm volatile("cp.async.commit_group;" ::: "memory");                       \
} while (0)

    const int wm = (wid & 3) << 5, wn = (wid >> 2) << 5;
    const int rA = lane & 15, cA = (lane >> 4) << 3;
    const int rB = (lane & 7) + ((lane >> 4) << 3);
    const int cB = ((lane >> 3) & 1) << 3;

    float c[2][4][4];
#pragma unroll
    for (int i = 0; i < 2; i++)
#pragma unroll
        for (int j = 0; j < 4; j++)
#pragma unroll
            for (int r = 0; r < 4; r++) c[i][j][r] = 0.f;

    WV_LOAD(0, 0);
    for (int kb = 0; kb < 16; ++kb) {
        if (kb < 15) {
            WV_LOAD((kb + 1) & 1, kb + 1);
            asm volatile("cp.async.wait_group 1;" ::: "memory");
        } else {
            asm volatile("cp.async.wait_group 0;" ::: "memory");
        }
        __syncthreads();
        const uint32_t aS = aB + (uint32_t)(kb & 1) * WV_ASTG;
        const uint32_t bS = bB + (uint32_t)(kb & 1) * WV_BSTG;
#pragma unroll
        for (int ks = 0; ks < 4; ++ks) {
            uint32_t a[2][4];
#pragma unroll
            for (int i = 0; i < 2; i++)
                ldsm4(a[i], aS + (uint32_t)(((wm + i * 16 + rA) * 72 + cA + ks * 16) << 1));
            uint32_t bb[4][2];
#pragma unroll
            for (int j2 = 0; j2 < 2; j2++) {
                uint32_t r4[4];
                ldsm4(r4, bS + (uint32_t)(((wn + j2 * 16 + rB) * 72 + cB + ks * 16) << 1));
                bb[2 * j2 + 0][0] = r4[0]; bb[2 * j2 + 0][1] = r4[1];
                bb[2 * j2 + 1][0] = r4[2]; bb[2 * j2 + 1][1] = r4[3];
            }
#pragma unroll
            for (int i = 0; i < 2; i++)
#pragma unroll
                for (int j = 0; j < 4; j++)
                    mma16(c[i][j], a[i], bb[j]);
        }
        __syncthreads();
    }
#undef WV_LOAD

    const int gro = lane >> 2, gco = (lane & 3) << 1;
#pragma unroll
    for (int i = 0; i < 2; i++) {
        const int r0 = m0 + wm + i * 16 + gro;
        const float ps0 = psum[(size_t)r0 * 16 + h];
        const float ps1 = psum[(size_t)(r0 + 8) * 16 + h];
#pragma unroll
        for (int j = 0; j < 4; j++) {
            const int d = wn + j * 8 + gco;
            const float bv0 = sbv[d], bv1 = sbv[d + 1];
            __half* p0 = merged + ((size_t)r0 << 10) + (h << 6) + d;
            __half* p1 = merged + ((size_t)(r0 + 8) << 10) + (h << 6) + d;
            float2 o0 = __half22float2(*(__half2*)p0);
            float2 o1 = __half22float2(*(__half2*)p1);
            *(__half2*)p0 = __floats2half2_rn(o0.x + c[i][j][0] + ps0 * bv0,
                                              o0.y + c[i][j][1] + ps0 * bv1);
            *(__half2*)p1 = __floats2half2_rn(o1.x + c[i][j][2] + ps1 * bv0,
                                              o1.y + c[i][j][3] + ps1 * bv1);
        }
    }
}

// ---------------------------------------------------------------------------
// launch
// ---------------------------------------------------------------------------
extern "C" void kernel_launch(void* const* d_in, const int* in_sizes, int n_in,
                              void* d_out, int out_size)
{
    const float* x     = (const float*)d_in[0];
    const float* pastk = (const float*)d_in[1];
    const float* pastv = (const float*)d_in[2];
    const float* pastq = (const float*)d_in[3];
    const float* Wqkv  = (const float*)d_in[4];
    const float* bqkv  = (const float*)d_in[5];
    const float* Wout  = (const float*)d_in[6];
    const float* bout  = (const float*)d_in[7];

    float* out = (float*)d_out;                 // (B,S,D)
    float* oK  = out + (size_t)2097152;         // (B,H,S,hd)
    float* oV  = out + (size_t)2 * 2097152;
    float* oQ  = out + (size_t)3 * 2097152;

    static __half *s_memlnh = nullptr, *s_xh = nullptr, *s_wqkvh = nullptr;
    static __half *s_qh = nullptr, *s_kh = nullptr, *s_vh = nullptr;
    static __half *s_wkT = nullptr, *s_qp = nullptr, *s_ctx = nullptr;
    static __half *s_mergedh = nullptr, *s_wouth = nullptr;
    static float *s_ms = nullptr, *s_pmn = nullptr, *s_qb = nullptr;
    static float *s_psum = nullptr;
    if (!s_memlnh) {
        cudaGetSymbolAddress((void**)&s_memlnh, g_memlnh);
        cudaGetSymbolAddress((void**)&s_xh, g_xh);
        cudaGetSymbolAddress((void**)&s_wqkvh, g_wqkvh);
        cudaGetSymbolAddress((void**)&s_qh, g_qhh);
        cudaGetSymbolAddress((void**)&s_kh, g_khh);
        cudaGetSymbolAddress((void**)&s_vh, g_vhh);
        cudaGetSymbolAddress((void**)&s_wkT, g_wkT);
        cudaGetSymbolAddress((void**)&s_qp, g_qp);
        cudaGetSymbolAddress((void**)&s_ctx, g_ctx);
        cudaGetSymbolAddress((void**)&s_mergedh, g_mergedh);
        cudaGetSymbolAddress((void**)&s_wouth, g_wouth);
        cudaGetSymbolAddress((void**)&s_ms, g_ms);
        cudaGetSymbolAddress((void**)&s_pmn, g_pmn);
        cudaGetSymbolAddress((void**)&s_qb, g_qb);
        cudaGetSymbolAddress((void**)&s_psum, g_psum);
        cudaFuncSetAttribute(gemm_qkv, cudaFuncAttributeMaxDynamicSharedMemorySize,
                             GF_SMEM);
        cudaFuncSetAttribute(k_wv, cudaFuncAttributeMaxDynamicSharedMemorySize,
                             WV_SMEM);
        cudaFuncSetAttribute(gemm_h16, cudaFuncAttributeMaxDynamicSharedMemorySize,
                             GH_SMEM);
    }

    // 0) operand conversion
    cvt_fp16_kernel<<<2048, 256>>>((const float4*)x,    (__half2*)s_xh);
    cvt_fp16_kernel<<<3072, 256>>>((const float4*)Wqkv, (__half2*)s_wqkvh);
    cvt_fp16_kernel<<<1024, 256>>>((const float4*)Wout, (__half2*)s_wouth);
    {
        dim3 g(32, 32); dim3 blk(32, 8);
        k_wkT<<<g, blk>>>(Wqkv + (size_t)1024 * 1024, s_wkT);
    }

    // 1) qkv projection
    {
        dim3 g(3072 / 128, 2048 / 256);
        gemm_qkv<<<g, 256, GF_SMEM>>>(s_xh, s_wqkvh, bqkv, oQ, oK, oV,
                                      s_qh, s_kh, s_vh);
    }
    // 2) mem gather + LayerNorm -> fp16
    mem_ln_kernel<<<24576, 256>>>(pastq, pastk, pastv);
    // 3) per-head q projection, bias dots, mem scores
    {
        dim3 g(8, 8, 32);
        k_qp<<<g, 256>>>(s_qh, s_wkT, s_qp);
    }
    k_qb<<<32, 256>>>(s_qh, bqkv, s_qb);
    k_ms<<<2048, 512>>>(s_qp, s_memlnh, s_qb, s_ms);
    // 4) flash attention + merge (fp16 merged)
    {
        dim3 g(BATCH * NHEAD, 16);
        attn_fa<<<g, 128>>>(s_qh, s_kh, s_vh, s_ms, s_pmn, s_mergedh);
    }
    // 5) memory context: combine memln, apply Wv, accumulate into merged
    k_ctx<<<2048, 256>>>(s_pmn, s_memlnh, s_ctx, s_psum);
    {
        dim3 g(16, 16);
        k_wv<<<g, 256, WV_SMEM>>>(s_ctx, s_wqkvh, s_psum, bqkv, s_mergedh);
    }
    // 6) output projection (fp16 tensor core)
    {
        dim3 g(1024 / 128, 2048 / 128);
        gemm_h16<<<g, 256, GH_SMEM>>>(s_mergedh, s_wouth, bout, out,
                                      2048, 1024, 1024);
    }
}

// round 17
// speedup vs baseline: 1.0122x; 1.0122x over previous
#include <cuda_runtime.h>
#include <cuda_fp16.h>
#include <cstdint>

// Problem constants
#define BATCH   2
#define S_LEN   1024
#define D_DIM   1024
#define NHEAD   16
#define HD      64
#define NMEM    12          // 3*L
#define SCALE   0.125f      // 1/sqrt(64)

// ---------------------------------------------------------------------------
// Scratch (device globals: allocation-free)
// ---------------------------------------------------------------------------
__device__ __align__(16) __half g_memlnh[(size_t)24576 * 1024]; // LN'd mem rows (fp16)
__device__ __align__(16) __half g_xh    [(size_t)2048 * 1024];  // fp16 x
__device__ __align__(16) __half g_wqkvh [(size_t)3072 * 1024];  // fp16 Wqkv
__device__ __align__(16) __half g_qhh   [(size_t)2048 * 1024];  // fp16 q (B,H,S,hd)
__device__ __align__(16) __half g_khh   [(size_t)2048 * 1024];  // fp16 k
__device__ __align__(16) __half g_vhh   [(size_t)2048 * 1024];  // fp16 v
__device__ __align__(16) __half g_wkT   [(size_t)1024 * 1024];  // fp16 Wk^T
__device__ __align__(16) __half g_qp    [(size_t)2048 * 16 * 1024]; // Wk^T q per (bs,h)
__device__ __align__(16) __half g_ctx   [(size_t)2048 * 16 * 1024]; // sum_m w_m*memln
__device__ __align__(16) __half g_mergedh[(size_t)2048 * 1024]; // (B*S, D) attn out fp16
__device__ __align__(16) __half g_wouth [(size_t)1024 * 1024];  // fp16 Wout
__device__ float g_ms  [(size_t)2048 * 16 * 12];  // mem scores
__device__ float g_pmn [(size_t)2048 * 16 * 12];  // normalized mem weights
__device__ float g_qb  [(size_t)2048 * 16];       // q . bk_h
__device__ float g_psum[(size_t)2048 * 16];       // sum_m pmn

// ---------------------------------------------------------------------------
// Helpers
// ---------------------------------------------------------------------------
__device__ __forceinline__ uint32_t smem_u32(const void* p) {
    uint32_t a;
    asm("{ .reg .u64 t; cvta.to.shared.u64 t, %1; cvt.u32.u64 %0, t; }" : "=r"(a) : "l"(p));
    return a;
}
__device__ __forceinline__ void cp16(uint32_t dst, const void* src) {
    asm volatile("cp.async.cg.shared.global [%0], [%1], 16;" :: "r"(dst), "l"(src));
}
__device__ __forceinline__ void ldsm4(uint32_t* r, uint32_t addr) {
    asm volatile("ldmatrix.sync.aligned.m8n8.x4.shared.b16 {%0,%1,%2,%3}, [%4];"
                 : "=r"(r[0]), "=r"(r[1]), "=r"(r[2]), "=r"(r[3]) : "r"(addr));
}
__device__ __forceinline__ void ldsm4t(uint32_t* r, uint32_t addr) {
    asm volatile("ldmatrix.sync.aligned.m8n8.x4.trans.shared.b16 {%0,%1,%2,%3}, [%4];"
                 : "=r"(r[0]), "=r"(r[1]), "=r"(r[2]), "=r"(r[3]) : "r"(addr));
}
__device__ __forceinline__ void mma16(float* c, const uint32_t* a, const uint32_t* b) {
    asm volatile("mma.sync.aligned.m16n8k16.row.col.f32.f16.f16.f32 "
                 "{%0,%1,%2,%3}, {%4,%5,%6,%7}, {%8,%9}, {%0,%1,%2,%3};"
                 : "+f"(c[0]), "+f"(c[1]), "+f"(c[2]), "+f"(c[3])
                 : "r"(a[0]), "r"(a[1]), "r"(a[2]), "r"(a[3]), "r"(b[0]), "r"(b[1]));
}
__device__ __forceinline__ uint32_t packh2(float a, float b) {
    __half2 h = __floats2half2_rn(a, b);
    return *(uint32_t*)&h;
}

// ===========================================================================
// fp16 GEMM (NT) — GEMM1 only: qkv projection with scatter epilogue
// ===========================================================================
#define GF_ASTG 36864u
#define GF_BSTG 18432u
#define GF_SMEM 165888

__global__ void __launch_bounds__(256, 1)
gemm_qkv(const __half* __restrict__ A, const __half* __restrict__ B,
         const float* __restrict__ bias,
         float* __restrict__ oQ, float* __restrict__ oK, float* __restrict__ oV,
         __half* __restrict__ oQh, __half* __restrict__ oKh, __half* __restrict__ oVh)
{
    extern __shared__ char smemc[];
    const uint32_t aBase = smem_u32(smemc);
    const uint32_t bBase = aBase + 3u * GF_ASTG;
    const int K = 1024;

    const int tid = threadIdx.x;
    const int lane = tid & 31, wid = tid >> 5;
    const int m0 = blockIdx.y << 8;
    const int n0 = blockIdx.x << 7;
    const int wm = (wid & 3) << 6;
    const int wn = (wid >> 2) << 6;

    const int grow = tid >> 3;
    const int gc8  = (tid & 7) << 3;
    const __half* Ag = A + (size_t)(m0 + grow) * K + gc8;
    const __half* Bg = B + (size_t)(n0 + grow) * K + gc8;
    const uint32_t sOff = (uint32_t)((grow * 72 + gc8) << 1);

    const int rA = lane & 15, cA = (lane >> 4) << 3;
    const int rB = (lane & 7) + ((lane >> 4) << 3);
    const int cB = ((lane >> 3) & 1) << 3;

#define GF_LOAD(stage, kb) do {                                                \
    const __half* _a = Ag + ((kb) << 6);                                       \
    const __half* _b = Bg + ((kb) << 6);                                       \
    const uint32_t _da = aBase + (uint32_t)(stage) * GF_ASTG + sOff;           \
    const uint32_t _db = bBase + (uint32_t)(stage) * GF_BSTG + sOff;           \
    _Pragma("unroll")                                                          \
    for (int _p = 0; _p < 8; _p++)                                             \
        cp16(_da + (uint32_t)_p * 4608u, _a + (size_t)(_p << 5) * K);          \
    _Pragma("unroll")                                                          \
    for (int _p = 0; _p < 4; _p++)                                             \
        cp16(_db + (uint32_t)_p * 4608u, _b + (size_t)(_p << 5) * K);          \
    asm volatile("cp.async.commit_group;" ::: "memory");                       \
} while (0)

    float c[4][8][4];
#pragma unroll
    for (int i = 0; i < 4; i++)
#pragma unroll
        for (int j = 0; j < 8; j++)
#pragma unroll
            for (int r = 0; r < 4; r++) c[i][j][r] = 0.f;

    const int NK = 16;
    GF_LOAD(0, 0);
    GF_LOAD(1, 1);

    for (int kb = 0; kb < NK; ++kb) {
        if (kb < NK - 1)
            asm volatile("cp.async.wait_group 1;" ::: "memory");
        else
            asm volatile("cp.async.wait_group 0;" ::: "memory");
        __syncthreads();

        if (kb + 2 < NK) {
            int ns = kb + 2; ns = ns - (ns / 3) * 3;
            GF_LOAD(ns, kb + 2);
        }

        int st = kb - (kb / 3) * 3;
        const uint32_t aS = aBase + (uint32_t)st * GF_ASTG;
        const uint32_t bS = bBase + (uint32_t)st * GF_BSTG;

#pragma unroll
        for (int ks = 0; ks < 4; ++ks) {
            uint32_t a[4][4];
#pragma unroll
            for (int i = 0; i < 4; i++)
                ldsm4(a[i], aS + (uint32_t)(((wm + i * 16 + rA) * 72 + cA + ks * 16) << 1));
            uint32_t b[8][2];
#pragma unroll
            for (int j2 = 0; j2 < 4; j2++) {
                uint32_t r4[4];
                ldsm4(r4, bS + (uint32_t)(((wn + j2 * 16 + rB) * 72 + cB + ks * 16) << 1));
                b[2 * j2 + 0][0] = r4[0]; b[2 * j2 + 0][1] = r4[1];
                b[2 * j2 + 1][0] = r4[2]; b[2 * j2 + 1][1] = r4[3];
            }
#pragma unroll
            for (int i = 0; i < 4; i++)
#pragma unroll
                for (int j = 0; j < 8; j++)
                    mma16(c[i][j], a[i], b[j]);
        }
    }
#undef GF_LOAD

    const int gro = lane >> 2;
    const int gco = (lane & 3) << 1;
#pragma unroll
    for (int i = 0; i < 4; i++) {
        const int r0 = m0 + wm + i * 16 + gro;
#pragma unroll
        for (int j = 0; j < 8; j++) {
            const int col = n0 + wn + j * 8 + gco;
            const float b0 = bias[col], b1 = bias[col + 1];
            const int part = col >> 10;
            const int rem  = col & 1023;
            const int h = rem >> 6, d = rem & 63;
            float* dst = (part == 0) ? oQ : (part == 1) ? oK : oV;
            __half* dsth = (part == 0) ? oQh : (part == 1) ? oKh : oVh;
#pragma unroll
            for (int half = 0; half < 2; half++) {
                const int row = r0 + half * 8;
                const int bb = row >> 10, s = row & 1023;
                float vx = c[i][j][2 * half] + b0;
                float vy = c[i][j][2 * half + 1] + b1;
                const size_t idx = (size_t)(((bb * NHEAD + h) << 10) + s) * HD + d;
                *(float2*)(dst + idx) = make_float2(vx, vy);
                *(__half2*)(dsth + idx) = __floats2half2_rn(vx, vy);
            }
        }
    }
}

// ===========================================================================
// gemm_h16 — fp16 128x128 GEMM (NT) for GEMM3: out = merged @ Wout^T + bout
// ===========================================================================
#define GH_STG  18432u
#define GH_SMEM 73728

__global__ void __launch_bounds__(256)
gemm_h16(const __half* __restrict__ A, const __half* __restrict__ B,
         const float* __restrict__ bias, float* __restrict__ C,
         int M, int N, int K)
{
    extern __shared__ char smemc[];
    const uint32_t aBase = smem_u32(smemc);
    const uint32_t bBase = aBase + 2u * GH_STG;

    const int tid = threadIdx.x;
    const int lane = tid & 31, wid = tid >> 5;
    const int m0 = blockIdx.y << 7, n0 = blockIdx.x << 7;
    const int wm = (wid & 1) << 6;
    const int wn = (wid >> 1) << 5;

    const int grow = tid >> 1;
    const int gc = (tid & 1) << 5;
    const __half* Ag = A + (size_t)(m0 + grow) * K + gc;
    const __half* Bg = B + (size_t)(n0 + grow) * K + gc;
    const uint32_t sOff = (uint32_t)((grow * 72 + gc) << 1);

    const int rA = lane & 15, cA = (lane >> 4) << 3;
    const int rB = (lane & 7) + ((lane >> 4) << 3);
    const int cB = ((lane >> 3) & 1) << 3;

#define GH_LOAD(st, kb) do {                                                   \
    const __half* _a = Ag + ((kb) << 6);                                       \
    const __half* _b = Bg + ((kb) << 6);                                       \
    uint32_t _da = aBase + (uint32_t)(st) * GH_STG + sOff;                     \
    uint32_t _db = bBase + (uint32_t)(st) * GH_STG + sOff;                     \
    cp16(_da, _a); cp16(_da + 16, _a + 8);                                     \
    cp16(_da + 32, _a + 16); cp16(_da + 48, _a + 24);                          \
    cp16(_db, _b); cp16(_db + 16, _b + 8);                                     \
    cp16(_db + 32, _b + 16); cp16(_db + 48, _b + 24);                          \
    asm volatile("cp.async.commit_group;" ::: "memory");                       \
} while (0)

    float c[4][4][4];
#pragma unroll
    for (int i = 0; i < 4; i++)
#pragma unroll
        for (int j = 0; j < 4; j++)
#pragma unroll
            for (int r = 0; r < 4; r++) c[i][j][r] = 0.f;

    const int NK = K >> 6;
    GH_LOAD(0, 0);
    GH_LOAD(1, 1);

    for (int it = 0; it < NK; ++it) {
        if (it + 2 < NK)
            asm volatile("cp.async.wait_group 1;" ::: "memory");
        else
            asm volatile("cp.async.wait_group 0;" ::: "memory");
        __syncthreads();

        const int st = it & 1;
        const uint32_t aS = aBase + (uint32_t)st * GH_STG;
        const uint32_t bS = bBase + (uint32_t)st * GH_STG;

#pragma unroll
        for (int ks = 0; ks < 4; ++ks) {
            uint32_t a[4][4];
#pragma unroll
            for (int i = 0; i < 4; i++)
                ldsm4(a[i], aS + (uint32_t)(((wm + i * 16 + rA) * 72 + cA + ks * 16) << 1));
            uint32_t b[4][2];
#pragma unroll
            for (int j2 = 0; j2 < 2; j2++) {
                uint32_t r4[4];
                ldsm4(r4, bS + (uint32_t)(((wn + j2 * 16 + rB) * 72 + cB + ks * 16) << 1));
                b[2 * j2 + 0][0] = r4[0]; b[2 * j2 + 0][1] = r4[1];
                b[2 * j2 + 1][0] = r4[2]; b[2 * j2 + 1][1] = r4[3];
            }
#pragma unroll
            for (int i = 0; i < 4; i++)
#pragma unroll
                for (int j = 0; j < 4; j++)
                    mma16(c[i][j], a[i], b[j]);
        }
        __syncthreads();
        if (it + 2 < NK) GH_LOAD(st, it + 2);
    }
#undef GH_LOAD

    const int gro = lane >> 2;
    const int gco = (lane & 3) << 1;
#pragma unroll
    for (int i = 0; i < 4; i++) {
        const int r0 = m0 + wm + i * 16 + gro;
#pragma unroll
        for (int j = 0; j < 4; j++) {
            const int col = n0 + wn + j * 8 + gco;
            const float b0 = bias[col], b1 = bias[col + 1];
            float2 v0 = make_float2(c[i][j][0] + b0, c[i][j][1] + b1);
            float2 v1 = make_float2(c[i][j][2] + b0, c[i][j][3] + b1);
            *(float2*)(C + (size_t)r0 * N + col) = v0;
            *(float2*)(C + (size_t)(r0 + 8) * N + col) = v1;
        }
    }
}

// ---------------------------------------------------------------------------
// conversion / transpose kernels
// ---------------------------------------------------------------------------
__global__ void cvt_fp16_kernel(const float4* __restrict__ in, __half2* __restrict__ out)
{
    int i = blockIdx.x * blockDim.x + threadIdx.x;
    float4 v = in[i];
    out[2 * i + 0] = __floats2half2_rn(v.x, v.y);
    out[2 * i + 1] = __floats2half2_rn(v.z, v.w);
}
// Wk^T: o[n][j] = Wk[j][n]  (Wk = Wqkv rows 1024..2047), fp16 output
__global__ void k_wkT(const float* __restrict__ wk, __half* __restrict__ o)
{
    __shared__ float t[32][33];
    int x = (blockIdx.x << 5) + threadIdx.x;
    int y = (blockIdx.y << 5) + threadIdx.y;
#pragma unroll
    for (int i = 0; i < 32; i += 8)
        t[threadIdx.y + i][threadIdx.x] = wk[(size_t)(y + i) * 1024 + x];
    __syncthreads();
    x = (blockIdx.y << 5) + threadIdx.x;
    y = (blockIdx.x << 5) + threadIdx.y;
#pragma unroll
    for (int i = 0; i < 32; i += 8)
        o[(size_t)(y + i) * 1024 + x] = __float2half_rn(t[threadIdx.x][threadIdx.y + i]);
}

// ---------------------------------------------------------------------------
// Gather mem rows + LayerNorm -> fp16  (float4 per thread)
// ---------------------------------------------------------------------------
__device__ __forceinline__ float blockReduceSum(float v, float* red)
{
    __syncthreads();
    int lane = threadIdx.x & 31, wid = threadIdx.x >> 5;
#pragma unroll
    for (int o = 16; o; o >>= 1) v += __shfl_xor_sync(0xffffffffu, v, o);
    if (lane == 0) red[wid] = v;
    __syncthreads();
    if (wid == 0) {
        v = (lane < 8) ? red[lane] : 0.f;
#pragma unroll
        for (int o = 4; o; o >>= 1) v += __shfl_xor_sync(0xffffffffu, v, o);
        if (lane == 0) red[0] = v;
    }
    __syncthreads();
    return red[0];
}

__global__ void mem_ln_kernel(const float* __restrict__ pq,
                              const float* __restrict__ pk,
                              const float* __restrict__ pv)
{
    __shared__ float red[32];
    int row = blockIdx.x;
    int j  = row % NMEM;
    int bs = row / NMEM;
    int s = bs & 1023, b = bs >> 10;
    int l = j & 3;
    const float* src = (j < 4) ? pq : (j < 8) ? pk : pv;
    size_t base = (size_t)(l * BATCH + b) * (NHEAD * S_LEN * HD) + (size_t)s * HD;

    const int t = threadIdx.x;
    const int c0 = t << 2;
    const int h = c0 >> 6, d = c0 & 63;
    float4 v = __ldg((const float4*)(src + base + (size_t)h * (S_LEN * HD) + d));
    float sum = v.x + v.y + v.z + v.w;
    sum = blockReduceSum(sum, red);
    float mean = sum * (1.f / 1024.f);
    float4 dv = make_float4(v.x - mean, v.y - mean, v.z - mean, v.w - mean);
    float sq = dv.x * dv.x + dv.y * dv.y + dv.z * dv.z + dv.w * dv.w;
    sq = blockReduceSum(sq, red);
    float inv = rsqrtf(sq * (1.f / 1024.f) + 1e-5f);

    __half* orow = g_memlnh + (size_t)row * 1024;
    __half2 h0 = __floats2half2_rn(dv.x * inv, dv.y * inv);
    __half2 h1 = __floats2half2_rn(dv.z * inv, dv.w * inv);
    *(__half2*)(orow + c0)     = h0;
    *(__half2*)(orow + c0 + 2) = h1;
}

// ===========================================================================
// k_qp: qp[(bs,h),n] = sum_d q[b,h,s,d] * WkT[n, h*64+d]   (per-head proj)
// ===========================================================================
__global__ void __launch_bounds__(256)
k_qp(const __half* __restrict__ q, const __half* __restrict__ wkT,
     __half* __restrict__ qp)
{
    __shared__ __half sA[128 * 72];
    __shared__ __half sB[128 * 72];
    const int tid = threadIdx.x, lane = tid & 31, wid = tid >> 5;
    const int z = blockIdx.z, b = z >> 4, h = z & 15;
    const int m0 = blockIdx.y << 7, n0 = blockIdx.x << 7;
    const uint32_t aB = smem_u32(sA), bB = smem_u32(sB);

    {
        const int grow = tid >> 1, gc = (tid & 1) << 5;
        const __half* aSrc = q + ((size_t)z << 16) + ((size_t)(m0 + grow) << 6) + gc;
        const __half* bSrc = wkT + (size_t)(n0 + grow) * 1024 + (h << 6) + gc;
        uint32_t da = aB + (uint32_t)((grow * 72 + gc) << 1);
        uint32_t db = bB + (uint32_t)((grow * 72 + gc) << 1);
        cp16(da, aSrc); cp16(da + 16, aSrc + 8);
        cp16(da + 32, aSrc + 16); cp16(da + 48, aSrc + 24);
        cp16(db, bSrc); cp16(db + 16, bSrc + 8);
        cp16(db + 32, bSrc + 16); cp16(db + 48, bSrc + 24);
        asm volatile("cp.async.commit_group;\ncp.async.wait_group 0;" ::: "memory");
    }
    __syncthreads();

    const int wm = (wid & 1) << 6, wn = (wid >> 1) << 5;
    const int rA = lane & 15, cA = (lane >> 4) << 3;
    const int rB = (lane & 7) + ((lane >> 4) << 3);
    const int cB = ((lane >> 3) & 1) << 3;

    float c[4][4][4];
#pragma unroll
    for (int i = 0; i < 4; i++)
#pragma unroll
        for (int j = 0; j < 4; j++)
#pragma unroll
            for (int r = 0; r < 4; r++) c[i][j][r] = 0.f;

#pragma unroll
    for (int ks = 0; ks < 4; ++ks) {
        uint32_t a[4][4];
#pragma unroll
        for (int i = 0; i < 4; i++)
            ldsm4(a[i], aB + (uint32_t)(((wm + i * 16 + rA) * 72 + cA + ks * 16) << 1));
        uint32_t bb[4][2];
#pragma unroll
        for (int j2 = 0; j2 < 2; j2++) {
            uint32_t r4[4];
            ldsm4(r4, bB + (uint32_t)(((wn + j2 * 16 + rB) * 72 + cB + ks * 16) << 1));
            bb[2 * j2 + 0][0] = r4[0]; bb[2 * j2 + 0][1] = r4[1];
            bb[2 * j2 + 1][0] = r4[2]; bb[2 * j2 + 1][1] = r4[3];
        }
#pragma unroll
        for (int i = 0; i < 4; i++)
#pragma unroll
            for (int j = 0; j < 4; j++)
                mma16(c[i][j], a[i], bb[j]);
    }

    const int gro = lane >> 2, gco = (lane & 3) << 1;
#pragma unroll
    for (int i = 0; i < 4; i++) {
        const int row = m0 + wm + i * 16 + gro;
        __half* d0 = qp + ((size_t)((b << 10) + row) * 16 + h) * 1024;
        __half* d1 = d0 + (size_t)8 * 16 * 1024;
#pragma unroll
        for (int j = 0; j < 4; j++) {
            const int col = n0 + wn + j * 8 + gco;
            *(__half2*)(d0 + col) = __floats2half2_rn(c[i][j][0], c[i][j][1]);
            *(__half2*)(d1 + col) = __floats2half2_rn(c[i][j][2], c[i][j][3]);
        }
    }
}

// ===========================================================================
// k_qb: qb[(bs,h)] = q[b,h,s,:] . bqkv[1024 + h*64 ..]
// ===========================================================================
__global__ void k_qb(const __half* __restrict__ q, const float* __restrict__ bqkv,
                     float* __restrict__ qb)
{
    __shared__ float sbk[64];
    const int z = blockIdx.x, b = z >> 4, h = z & 15;
    if (threadIdx.x < 64) sbk[threadIdx.x] = bqkv[1024 + (h << 6) + threadIdx.x];
    __syncthreads();
    for (int s = threadIdx.x; s < 1024; s += 256) {
        const __half2* qr = (const __half2*)(q + ((size_t)z << 16) + ((size_t)s << 6));
        float acc = 0.f;
#pragma unroll
        for (int i = 0; i < 32; i++) {
            float2 f = __half22float2(qr[i]);
            acc += f.x * sbk[2 * i] + f.y * sbk[2 * i + 1];
        }
        qb[(size_t)((b << 10) + s) * 16 + h] = acc;
    }
}

// ===========================================================================
// k_ms: mem scores[(bs,h),m] = (qp[bs,h,:].memln[bs,m,:] + qb)*SCALE
// ===========================================================================
__global__ void __launch_bounds__(512)
k_ms(const __half* __restrict__ qp, const __half* __restrict__ memln,
     const float* __restrict__ qb, float* __restrict__ ms)
{
    __shared__ __align__(16) __half sm[12 * 1024];
    const int bs = blockIdx.x;
    const int tid = threadIdx.x, lane = tid & 31, w = tid >> 5;
    const __half* mlb = memln + (size_t)bs * 12288;
    for (int u = tid; u < 1536; u += 512)
        ((float4*)sm)[u] = ((const float4*)mlb)[u];

    const __half* qpr = qp + ((size_t)bs * 16 + w) * 1024;
    float4 qf[4];
#pragma unroll
    for (int i = 0; i < 4; i++) qf[i] = ((const float4*)qpr)[i * 32 + lane];
    __syncthreads();

    const float qbv = qb[(size_t)bs * 16 + w];
#pragma unroll
    for (int m = 0; m < NMEM; m++) {
        float acc = 0.f;
#pragma unroll
        for (int i = 0; i < 4; i++) {
            float4 mf = ((const float4*)sm)[m * 128 + i * 32 + lane];
            const __half2* qh2 = (const __half2*)&qf[i];
            const __half2* mh2 = (const __half2*)&mf;
#pragma unroll
            for (int jj = 0; jj < 4; jj++) {
                float2 a = __half22float2(qh2[jj]);
                float2 c2 = __half22float2(mh2[jj]);
                acc += a.x * c2.x + a.y * c2.y;
            }
        }
#pragma unroll
        for (int o = 16; o; o >>= 1) acc += __shfl_xor_sync(0xffffffffu, acc, o);
        if (lane == 0) ms[((size_t)bs * 16 + w) * 12 + m] = (acc + qbv) * SCALE;
    }
}

// ===========================================================================
// Flash attention (fp16 tc) token part + merge with precomputed mem scores.
// ===========================================================================
__global__ void __launch_bounds__(128)
attn_fa(const __half* __restrict__ qh, const __half* __restrict__ kh,
        const __half* __restrict__ vh, const float* __restrict__ ms,
        float* __restrict__ pmn, __half* __restrict__ merged)
{
    __shared__ __half sQ[64 * 72];
    __shared__ __half sK[2][64 * 72];
    __shared__ __half sV[2][64 * 72];

    const int tid = threadIdx.x;
    const int lane = tid & 31, w = tid >> 5;
    const int bh = blockIdx.x, b = bh >> 4, h = bh & 15;
    const int qt = gridDim.y - 1 - blockIdx.y;
    const int q0 = qt << 6;
    const int wr = w << 4;

    const uint32_t sQb = smem_u32(sQ);
    const uint32_t sKb = smem_u32(sK);
    const uint32_t sVb = smem_u32(sV);

    const int lrow = tid >> 1;
    const int lcol = (tid & 1) << 5;
    const __half* qg = qh + ((size_t)bh << 16);
    const __half* kg = kh + ((size_t)bh << 16);
    const __half* vg = vh + ((size_t)bh << 16);

#define LOADKV(bf, kt_) do {                                                   \
    const __half* _ks = kg + (((kt_) * 64 + lrow) << 6) + lcol;                \
    const __half* _vs = vg + (((kt_) * 64 + lrow) << 6) + lcol;                \
    uint32_t _kd = sKb + (uint32_t)(bf) * 9216u + ((lrow * 72 + lcol) << 1);   \
    uint32_t _vd = sVb + (uint32_t)(bf) * 9216u + ((lrow * 72 + lcol) << 1);   \
    cp16(_kd, _ks); cp16(_kd + 16, _ks + 8);                                   \
    cp16(_kd + 32, _ks + 16); cp16(_kd + 48, _ks + 24);                        \
    cp16(_vd, _vs); cp16(_vd + 16, _vs + 8);                                   \
    cp16(_vd + 32, _vs + 16); cp16(_vd + 48, _vs + 24);                        \
    asm volatile("cp.async.commit_group;" ::: "memory");                       \
} while (0)

    {
        const __half* src = qg + ((q0 + lrow) << 6) + lcol;
        uint32_t dst = sQb + ((lrow * 72 + lcol) << 1);
        cp16(dst, src); cp16(dst + 16, src + 8);
        cp16(dst + 32, src + 16); cp16(dst + 48, src + 24);
    }
    LOADKV(0, 0);
    asm volatile("cp.async.wait_group 0;" ::: "memory");
    __syncthreads();

    uint32_t qa[4][4];
    {
        const int qm = lane >> 3, qr = lane & 7;
        const int qrow = wr + ((qm & 1) << 3) + qr;
        const int qcb = (qm >> 1) << 3;
#pragma unroll
        for (int ki = 0; ki < 4; ki++)
            ldsm4(qa[ki], sQb + ((qrow * 72 + qcb + ki * 16) << 1));
    }

    const int km = lane >> 3, kr = lane & 7;
    const int kro = ((km >> 1) & 1) << 3;
    const int kco = (km & 1) << 3;
    const int vko = (km & 1) << 3;
    const int vco = ((km >> 1) & 1) << 3;

    float o[8][4];
#pragma unroll
    for (int j = 0; j < 8; j++)
#pragma unroll
        for (int e = 0; e < 4; e++) o[j][e] = 0.f;
    float mrow[2] = { -1e30f, -1e30f };
    float lrow_[2] = { 0.f, 0.f };

    const int rlane = lane >> 2, clane = (lane & 3) << 1;

    for (int kt = 0; kt <= qt; ++kt) {
        if (kt < qt) {
            LOADKV((kt + 1) & 1, kt + 1);
            asm volatile("cp.async.wait_group 1;" ::: "memory");
        } else {
            asm volatile("cp.async.wait_group 0;" ::: "memory");
        }
        __syncthreads();

        const uint32_t kS = sKb + (uint32_t)(kt & 1) * 9216u;
        const uint32_t vS = sVb + (uint32_t)(kt & 1) * 9216u;

        float sc[8][4];
#pragma unroll
        for (int j = 0; j < 8; j++)
#pragma unroll
            for (int e = 0; e < 4; e++) sc[j][e] = 0.f;

#pragma unroll
        for (int ks = 0; ks < 4; ++ks) {
#pragma unroll
            for (int j2 = 0; j2 < 4; ++j2) {
                uint32_t kb[4];
                ldsm4(kb, kS + (((j2 * 16 + kro + kr) * 72 + ks * 16 + kco) << 1));
                mma16(sc[2 * j2], qa[ks], kb);
                mma16(sc[2 * j2 + 1], qa[ks], kb + 2);
            }
        }

#pragma unroll
        for (int j = 0; j < 8; j++)
#pragma unroll
            for (int e = 0; e < 4; e++) sc[j][e] *= SCALE;
        if (kt == qt) {
            const int r0 = wr + rlane;
#pragma unroll
            for (int j = 0; j < 8; j++) {
                const int c0 = 8 * j + clane;
                if (c0 > r0)     sc[j][0] = -1e30f;
                if (c0 + 1 > r0) sc[j][1] = -1e30f;
                if (c0 > r0 + 8)     sc[j][2] = -1e30f;
                if (c0 + 1 > r0 + 8) sc[j][3] = -1e30f;
            }
        }

        float t0 = -1e30f, t1 = -1e30f;
#pragma unroll
        for (int j = 0; j < 8; j++) {
            t0 = fmaxf(t0, fmaxf(sc[j][0], sc[j][1]));
            t1 = fmaxf(t1, fmaxf(sc[j][2], sc[j][3]));
        }
        t0 = fmaxf(t0, __shfl_xor_sync(0xffffffffu, t0, 1));
        t0 = fmaxf(t0, __shfl_xor_sync(0xffffffffu, t0, 2));
        t1 = fmaxf(t1, __shfl_xor_sync(0xffffffffu, t1, 1));
        t1 = fmaxf(t1, __shfl_xor_sync(0xffffffffu, t1, 2));
        const float mn0 = fmaxf(mrow[0], t0), mn1 = fmaxf(mrow[1], t1);
        const float cr0 = __expf(mrow[0] - mn0), cr1 = __expf(mrow[1] - mn1);
        float s0 = 0.f, s1 = 0.f;
#pragma unroll
        for (int j = 0; j < 8; j++) {
            sc[j][0] = __expf(sc[j][0] - mn0);
            sc[j][1] = __expf(sc[j][1] - mn0);
            sc[j][2] = __expf(sc[j][2] - mn1);
            sc[j][3] = __expf(sc[j][3] - mn1);
            s0 += sc[j][0] + sc[j][1];
            s1 += sc[j][2] + sc[j][3];
        }
        s0 += __shfl_xor_sync(0xffffffffu, s0, 1);
        s0 += __shfl_xor_sync(0xffffffffu, s0, 2);
        s1 += __shfl_xor_sync(0xffffffffu, s1, 1);
        s1 += __shfl_xor_sync(0xffffffffu, s1, 2);
        lrow_[0] = lrow_[0] * cr0 + s0;
        lrow_[1] = lrow_[1] * cr1 + s1;
        mrow[0] = mn0; mrow[1] = mn1;
#pragma unroll
        for (int j = 0; j < 8; j++) {
            o[j][0] *= cr0; o[j][1] *= cr0;
            o[j][2] *= cr1; o[j][3] *= cr1;
        }

#pragma unroll
        for (int kc = 0; kc < 4; ++kc) {
            uint32_t pa[4];
            pa[0] = packh2(sc[2 * kc][0], sc[2 * kc][1]);
            pa[1] = packh2(sc[2 * kc][2], sc[2 * kc][3]);
            pa[2] = packh2(sc[2 * kc + 1][0], sc[2 * kc + 1][1]);
            pa[3] = packh2(sc[2 * kc + 1][2], sc[2 * kc + 1][3]);
#pragma unroll
            for (int j2 = 0; j2 < 4; ++j2) {
                uint32_t vb[4];
                ldsm4t(vb, vS + (((kc * 16 + vko + kr) * 72 + j2 * 16 + vco) << 1));
                mma16(o[2 * j2], pa, vb);
                mma16(o[2 * j2 + 1], pa, vb + 2);
            }
        }
        __syncthreads();
    }
#undef LOADKV

#pragma unroll
    for (int hh = 0; hh < 2; hh++) {
        const int s_idx = q0 + wr + rlane + (hh << 3);
        const size_t bsh = (size_t)((b << 10) + s_idx) * 16 + h;
        const float* msp = ms + bsh * 12;
        float smv[12];
#pragma unroll
        for (int m = 0; m < NMEM; m++) smv[m] = msp[m];
        float mx = smv[0];
#pragma unroll
        for (int m = 1; m < NMEM; m++) mx = fmaxf(mx, smv[m]);
        const float mn = fmaxf(mrow[hh], mx);
        const float corr = __expf(mrow[hh] - mn);
        float p[12], ps = 0.f;
#pragma unroll
        for (int m = 0; m < NMEM; m++) { p[m] = __expf(smv[m] - mn); ps += p[m]; }
        const float lf = lrow_[hh] * corr + ps;
        const float inv = 1.f / lf;
        const float cf = corr * inv;
        if ((lane & 3) == 0) {
            float* pw = pmn + bsh * 12;
#pragma unroll
            for (int m = 0; m < NMEM; m++) pw[m] = p[m] * inv;
        }
        __half* op = merged + ((size_t)((b << 10) + s_idx) << 10) + (h << 6);
#pragma unroll
        for (int j = 0; j < 8; j++)
            *(__half2*)(op + 8 * j + clane) =
                __floats2half2_rn(o[j][2 * hh] * cf, o[j][2 * hh + 1] * cf);
    }
}

// ===========================================================================
// k_ctx: ctx[(bs,h),k] = sum_m pmn[(bs,h),m]*memln[bs,m,k]; psum[(bs,h)]
// ===========================================================================
__global__ void __launch_bounds__(256)
k_ctx(const float* __restrict__ pmn, const __half* __restrict__ memln,
      __half* __restrict__ ctx, float* __restrict__ psum)
{
    __shared__ __align__(16) __half sm[12 * 1024];
    __shared__ float sp[192];
    const int bs = blockIdx.x, tid = threadIdx.x;
    const __half* mlb = memln + (size_t)bs * 12288;
    for (int u = tid; u < 1536; u += 256)
        ((float4*)sm)[u] = ((const float4*)mlb)[u];
    if (tid < 192) sp[tid] = pmn[(size_t)bs * 192 + tid];
    __syncthreads();
    if (tid < 16) {
        float s = 0.f;
#pragma unroll
        for (int m = 0; m < NMEM; m++) s += sp[tid * 12 + m];
        psum[(size_t)bs * 16 + tid] = s;
    }
    float mv[12][4];
#pragma unroll
    for (int m = 0; m < NMEM; m++) {
        float2 fx = __half22float2(*(__half2*)&sm[m * 1024 + (tid << 2)]);
        float2 fy = __half22float2(*(__half2*)&sm[m * 1024 + (tid << 2) + 2]);
        mv[m][0] = fx.x; mv[m][1] = fx.y; mv[m][2] = fy.x; mv[m][3] = fy.y;
    }
#pragma unroll
    for (int h = 0; h < 16; h++) {
        float o0 = 0.f, o1 = 0.f, o2 = 0.f, o3 = 0.f;
#pragma unroll
        for (int m = 0; m < NMEM; m++) {
            const float p = sp[h * 12 + m];
            o0 += p * mv[m][0]; o1 += p * mv[m][1];
            o2 += p * mv[m][2]; o3 += p * mv[m][3];
        }
        __half2* dst = (__half2*)(ctx + ((size_t)bs * 16 + h) * 1024 + (tid << 2));
        dst[0] = __floats2half2_rn(o0, o1);
        dst[1] = __floats2half2_rn(o2, o3);
    }
}

// ===========================================================================
// k_wv: merged[bs, h*64+d] += sum_k Wv[h*64+d,k]*ctx[(bs,h),k] + psum*bv
// ===========================================================================
#define WV_ASTG 18432u
#define WV_BSTG 9216u
#define WV_SMEM (2 * (WV_ASTG + WV_BSTG))

__global__ void __launch_bounds__(256)
k_wv(const __half* __restrict__ ctx, const __half* __restrict__ wqkvh,
     const float* __restrict__ psum, const float* __restrict__ bqkv,
     __half* __restrict__ merged)
{
    extern __shared__ char smemc[];
    const uint32_t aB = smem_u32(smemc);
    const uint32_t bB = aB + 2u * WV_ASTG;
    __shared__ float sbv[64];

    const int tid = threadIdx.x, lane = tid & 31, wid = tid >> 5;
    const int m0 = blockIdx.x << 7, h = blockIdx.y;
    if (tid < 64) sbv[tid] = bqkv[2048 + (h << 6) + tid];

    const __half* A = ctx + (size_t)h * 1024;
    const __half* B = wqkvh + (size_t)(2048 + (h << 6)) * 1024;

    const int agrow = tid >> 1, agc = (tid & 1) << 5;
    const int bgrow = tid >> 2, bgc = (tid & 3) << 4;

#define WV_LOAD(st, kb) do {                                                   \
    const __half* _a = A + (size_t)(m0 + agrow) * 16384 + ((kb) << 6) + agc;   \
    const __half* _b = B + (size_t)bgrow * 1024 + ((kb) << 6) + bgc;           \
    uint32_t _da = aB + (uint32_t)(st) * WV_ASTG + ((agrow * 72 + agc) << 1);  \
    uint32_t _db = bB + (uint32_t)(st) * WV_BSTG + ((bgrow * 72 + bgc) << 1);  \
    cp16(_da, _a); cp16(_da + 16, _a + 8);                                     \
    cp16(_da + 32, _a + 16); cp16(_da + 48, _a + 24);                          \
    cp16(_db, _b); cp16(_db + 16, _b + 8);                                     \
    asm volatile("cp.async.commit_group;" ::: "memory");                       \
} while (0)

    const int wm = (wid & 3) << 5, wn = (wid >> 2) << 5;
    const int rA = lane & 15, cA = (lane >> 4) << 3;
    const int rB = (lane & 7) + ((lane >> 4) << 3);
    const int cB = ((lane >> 3) & 1) << 3;

    float c[2][4][4];
#pragma unroll
    for (int i = 0; i < 2; i++)
#pragma unroll
        for (int j = 0; j < 4; j++)
#pragma unroll
            for (int r = 0; r < 4; r++) c[i][j][r] = 0.f;

    WV_LOAD(0, 0);
    for (int kb = 0; kb < 16; ++kb) {
        if (kb < 15) {
            WV_LOAD((kb + 1) & 1, kb + 1);
            asm volatile("cp.async.wait_group 1;" ::: "memory");
        } else {
            asm volatile("cp.async.wait_group 0;" ::: "memory");
        }
        __syncthreads();
        const uint32_t aS = aB + (uint32_t)(kb & 1) * WV_ASTG;
        const uint32_t bS = bB + (uint32_t)(kb & 1) * WV_BSTG;
#pragma unroll
        for (int ks = 0; ks < 4; ++ks) {
            uint32_t a[2][4];
#pragma unroll
            for (int i = 0; i < 2; i++)
                ldsm4(a[i], aS + (uint32_t)(((wm + i * 16 + rA) * 72 + cA + ks * 16) << 1));
            uint32_t bb[4][2];
#pragma unroll
            for (int j2 = 0; j2 < 2; j2++) {
                uint32_t r4[4];
                ldsm4(r4, bS + (uint32_t)(((wn + j2 * 16 + rB) * 72 + cB + ks * 16) << 1));
                bb[2 * j2 + 0][0] = r4[0]; bb[2 * j2 + 0][1] = r4[1];
                bb[2 * j2 + 1][0] = r4[2]; bb[2 * j2 + 1][1] = r4[3];
            }
#pragma unroll
            for (int i = 0; i < 2; i++)
#pragma unroll
                for (int j = 0; j < 4; j++)
                    mma16(c[i][j], a[i], bb[j]);
        }
        __syncthreads();
    }
#undef WV_LOAD

    const int gro = lane >> 2, gco = (lane & 3) << 1;
#pragma unroll
    for (int i = 0; i < 2; i++) {
        const int r0 = m0 + wm + i * 16 + gro;
        const float ps0 = psum[(size_t)r0 * 16 + h];
        const float ps1 = psum[(size_t)(r0 + 8) * 16 + h];
#pragma unroll
        for (int j = 0; j < 4; j++) {
            const int d = wn + j * 8 + gco;
            const float bv0 = sbv[d], bv1 = sbv[d + 1];
            __half* p0 = merged + ((size_t)r0 << 10) + (h << 6) + d;
            __half* p1 = merged + ((size_t)(r0 + 8) << 10) + (h << 6) + d;
            float2 o0 = __half22float2(*(__half2*)p0);
            float2 o1 = __half22float2(*(__half2*)p1);
            *(__half2*)p0 = __floats2half2_rn(o0.x + c[i][j][0] + ps0 * bv0,
                                              o0.y + c[i][j][1] + ps0 * bv1);
            *(__half2*)p1 = __floats2half2_rn(o1.x + c[i][j][2] + ps1 * bv0,
                                              o1.y + c[i][j][3] + ps1 * bv1);
        }
    }
}

// ---------------------------------------------------------------------------
// launch — multi-stream DAG (forked capture). Streams/events created on the
// first (uncaptured) correctness call; during capture the event record/wait
// pairs become graph edges and all forks rejoin the origin stream.
// ---------------------------------------------------------------------------
extern "C" void kernel_launch(void* const* d_in, const int* in_sizes, int n_in,
                              void* d_out, int out_size)
{
    const float* x     = (const float*)d_in[0];
    const float* pastk = (const float*)d_in[1];
    const float* pastv = (const float*)d_in[2];
    const float* pastq = (const float*)d_in[3];
    const float* Wqkv  = (const float*)d_in[4];
    const float* bqkv  = (const float*)d_in[5];
    const float* Wout  = (const float*)d_in[6];
    const float* bout  = (const float*)d_in[7];

    float* out = (float*)d_out;                 // (B,S,D)
    float* oK  = out + (size_t)2097152;         // (B,H,S,hd)
    float* oV  = out + (size_t)2 * 2097152;
    float* oQ  = out + (size_t)3 * 2097152;

    static __half *s_memlnh = nullptr, *s_xh = nullptr, *s_wqkvh = nullptr;
    static __half *s_qh = nullptr, *s_kh = nullptr, *s_vh = nullptr;
    static __half *s_wkT = nullptr, *s_qp = nullptr, *s_ctx = nullptr;
    static __half *s_mergedh = nullptr, *s_wouth = nullptr;
    static float *s_ms = nullptr, *s_pmn = nullptr, *s_qb = nullptr;
    static float *s_psum = nullptr;
    static cudaStream_t stB = nullptr, stC = nullptr;
    static cudaEvent_t eRoot, eLN, eWk, eWo, eG, eQb;
    if (!s_memlnh) {
        cudaGetSymbolAddress((void**)&s_memlnh, g_memlnh);
        cudaGetSymbolAddress((void**)&s_xh, g_xh);
        cudaGetSymbolAddress((void**)&s_wqkvh, g_wqkvh);
        cudaGetSymbolAddress((void**)&s_qh, g_qhh);
        cudaGetSymbolAddress((void**)&s_kh, g_khh);
        cudaGetSymbolAddress((void**)&s_vh, g_vhh);
        cudaGetSymbolAddress((void**)&s_wkT, g_wkT);
        cudaGetSymbolAddress((void**)&s_qp, g_qp);
        cudaGetSymbolAddress((void**)&s_ctx, g_ctx);
        cudaGetSymbolAddress((void**)&s_mergedh, g_mergedh);
        cudaGetSymbolAddress((void**)&s_wouth, g_wouth);
        cudaGetSymbolAddress((void**)&s_ms, g_ms);
        cudaGetSymbolAddress((void**)&s_pmn, g_pmn);
        cudaGetSymbolAddress((void**)&s_qb, g_qb);
        cudaGetSymbolAddress((void**)&s_psum, g_psum);
        cudaFuncSetAttribute(gemm_qkv, cudaFuncAttributeMaxDynamicSharedMemorySize,
                             GF_SMEM);
        cudaFuncSetAttribute(k_wv, cudaFuncAttributeMaxDynamicSharedMemorySize,
                             WV_SMEM);
        cudaFuncSetAttribute(gemm_h16, cudaFuncAttributeMaxDynamicSharedMemorySize,
                             GH_SMEM);
        cudaStreamCreateWithFlags(&stB, cudaStreamNonBlocking);
        cudaStreamCreateWithFlags(&stC, cudaStreamNonBlocking);
        cudaEventCreateWithFlags(&eRoot, cudaEventDisableTiming);
        cudaEventCreateWithFlags(&eLN,   cudaEventDisableTiming);
        cudaEventCreateWithFlags(&eWk,   cudaEventDisableTiming);
        cudaEventCreateWithFlags(&eWo,   cudaEventDisableTiming);
        cudaEventCreateWithFlags(&eG,    cudaEventDisableTiming);
        cudaEventCreateWithFlags(&eQb,   cudaEventDisableTiming);
    }

    // ---- fork ----
    cudaEventRecord(eRoot, 0);
    cudaStreamWaitEvent(stB, eRoot, 0);
    cudaStreamWaitEvent(stC, eRoot, 0);

    // Track B: mem gather + LayerNorm (independent of x/weights path)
    mem_ln_kernel<<<24576, 256, 0, stB>>>(pastq, pastk, pastv);
    cudaEventRecord(eLN, stB);

    // Track C: weight-only preprocessing
    {
        dim3 g(32, 32); dim3 blk(32, 8);
        k_wkT<<<g, blk, 0, stC>>>(Wqkv + (size_t)1024 * 1024, s_wkT);
    }
    cudaEventRecord(eWk, stC);
    cvt_fp16_kernel<<<1024, 256, 0, stC>>>((const float4*)Wout, (__half2*)s_wouth);
    cudaEventRecord(eWo, stC);

    // Main track (origin stream): critical path
    cvt_fp16_kernel<<<2048, 256>>>((const float4*)x,    (__half2*)s_xh);
    cvt_fp16_kernel<<<3072, 256>>>((const float4*)Wqkv, (__half2*)s_wqkvh);
    {
        dim3 g(3072 / 128, 2048 / 256);
        gemm_qkv<<<g, 256, GF_SMEM>>>(s_xh, s_wqkvh, bqkv, oQ, oK, oV,
                                      s_qh, s_kh, s_vh);
    }
    cudaEventRecord(eG, 0);

    // Track C continues: k_qb (needs q fp16) overlaps k_qp on main
    cudaStreamWaitEvent(stC, eG, 0);
    k_qb<<<32, 256, 0, stC>>>(s_qh, bqkv, s_qb);
    cudaEventRecord(eQb, stC);

    // Main: per-head q projection (needs Wk^T)
    cudaStreamWaitEvent(0, eWk, 0);
    {
        dim3 g(8, 8, 32);
        k_qp<<<g, 256>>>(s_qh, s_wkT, s_qp);
    }
    // Main: mem scores (needs qp, memln, qb)
    cudaStreamWaitEvent(0, eLN, 0);
    cudaStreamWaitEvent(0, eQb, 0);
    k_ms<<<2048, 512>>>(s_qp, s_memlnh, s_qb, s_ms);
    // Main: flash attention + merge
    {
        dim3 g(BATCH * NHEAD, 16);
        attn_fa<<<g, 128>>>(s_qh, s_kh, s_vh, s_ms, s_pmn, s_mergedh);
    }
    // Main: memory context + Wv accumulate
    k_ctx<<<2048, 256>>>(s_pmn, s_memlnh, s_ctx, s_psum);
    {
        dim3 g(16, 16);
        k_wv<<<g, 256, WV_SMEM>>>(s_ctx, s_wqkvh, s_psum, bqkv, s_mergedh);
    }
    // Main: output projection (needs fp16 Wout — joins track C)
    cudaStreamWaitEvent(0, eWo, 0);
    {
        dim3 g(1024 / 128, 2048 / 128);
        gemm_h16<<<g, 256, GH_SMEM>>>(s_mergedh, s_wouth, bout, out,
                                      2048, 1024, 1024);
    }
}